// round 12
// baseline (speedup 1.0000x reference)
#include <cuda_runtime.h>
#include <cstdint>

#define N_NODES 100000
#define N_NODES_PAD 100096   // padded so GEMM A-tile loads never go OOB
#define N_EDGES 50000
#define NNZ     800000
#define C       256
#define C4      (C / 4)   // 64 float4 per row

// ---------------- scratch (__device__ globals: allowed) ----------------
__device__ float    g_m[(size_t)N_NODES_PAD * C];  // tf32-encoded (x0 + m)
__device__ uint32_t g_w[(size_t)C * C];            // tf32-encoded W
__device__ int   d_cnt_e[N_EDGES];
__device__ int   d_cnt_n[N_NODES];
__device__ int   d_off_e[N_EDGES + 1];
__device__ int   d_off_n[N_NODES + 1];
__device__ int   d_memb_e[NNZ];                // node ids grouped by edge
__device__ int   d_memb_n[NNZ];                // edge ids grouped by node

__device__ __forceinline__ uint32_t f2tf32(float f) {
    uint32_t r;
    asm("cvt.rna.tf32.f32 %0, %1;" : "=r"(r) : "f"(f));
    return r;
}

// ---------------------------------------------------------------------------
// 1. histogram (grid-stride, R8 form) + W->tf32 conversion folded in
// ---------------------------------------------------------------------------
__global__ void hist_kernel(const int* __restrict__ node_idx,
                            const int* __restrict__ edge_idx,
                            const float4* __restrict__ W) {
    int idx = blockIdx.x * blockDim.x + threadIdx.x;

    // fold W conversion into the first 64 blocks (16384 uint4 total)
    if (idx < C * C / 4) {
        float4 v = W[idx];
        uint4 t;
        t.x = f2tf32(v.x); t.y = f2tf32(v.y); t.z = f2tf32(v.z); t.w = f2tf32(v.w);
        reinterpret_cast<uint4*>(g_w)[idx] = t;
    }

    int stride = gridDim.x * blockDim.x;
    for (int i = idx; i < NNZ; i += stride) {
        atomicAdd(&d_cnt_e[edge_idx[i]], 1);
        atomicAdd(&d_cnt_n[node_idx[i]], 1);
    }
}

// ---------------------------------------------------------------------------
// 2. exclusive scan, VT=4 (int4), R8 form. block 0 -> edges, block 1 -> nodes.
// ---------------------------------------------------------------------------
__global__ __launch_bounds__(1024)
void scan_two_kernel() {
    int* cnt;
    int* off;
    int  L;
    if (blockIdx.x == 0) { cnt = d_cnt_e; off = d_off_e; L = N_EDGES; }
    else                 { cnt = d_cnt_n; off = d_off_n; L = N_NODES; }

    const int tid  = threadIdx.x;
    const int lane = tid & 31;
    const int wid  = tid >> 5;
    __shared__ int warp_sum[32];

    const int L4 = L >> 2;
    int running = 0;
    for (int base4 = 0; base4 < L4; base4 += 1024) {
        int i4 = base4 + tid;
        int4 v = make_int4(0, 0, 0, 0);
        if (i4 < L4) v = reinterpret_cast<const int4*>(cnt)[i4];
        int p0 = v.x;
        int p1 = p0 + v.y;
        int p2 = p1 + v.z;
        int p3 = p2 + v.w;
        int tot = p3;
        int w = tot;
        #pragma unroll
        for (int d = 1; d < 32; d <<= 1) {
            int t = __shfl_up_sync(0xffffffffu, w, d);
            if (lane >= d) w += t;
        }
        if (lane == 31) warp_sum[wid] = w;
        __syncthreads();
        if (wid == 0) {
            int ws = warp_sum[lane];
            #pragma unroll
            for (int d = 1; d < 32; d <<= 1) {
                int t = __shfl_up_sync(0xffffffffu, ws, d);
                if (lane >= d) ws += t;
            }
            warp_sum[lane] = ws;
        }
        __syncthreads();
        int excl = (w - tot) + (wid > 0 ? warp_sum[wid - 1] : 0) + running;
        if (i4 < L4) {
            int i = i4 * 4;
            off[i + 1] = excl + p0;
            off[i + 2] = excl + p1;
            off[i + 3] = excl + p2;
            off[i + 4] = excl + p3;
        }
        running += warp_sum[31];
        __syncthreads();
    }
    if (tid == 0) off[0] = 0;
    for (int i = tid; i < L; i += 1024) cnt[i] = 0;
}

// ---------------------------------------------------------------------------
// 3. fill member lists (rank via int atomics)
// ---------------------------------------------------------------------------
__global__ void fill_kernel(const int* __restrict__ node_idx,
                            const int* __restrict__ edge_idx) {
    int idx = blockIdx.x * blockDim.x + threadIdx.x;
    int stride = gridDim.x * blockDim.x;
    for (int i = idx; i < NNZ; i += stride) {
        int n = node_idx[i];
        int e = edge_idx[i];
        int re = atomicAdd(&d_cnt_e[e], 1);
        d_memb_e[d_off_e[e] + re] = n;
        int rn = atomicAdd(&d_cnt_n[n], 1);
        d_memb_n[d_off_n[n] + rn] = e;
    }
}

// ---------------------------------------------------------------------------
// 4. reduce v2e, channel-split: pass y covers float4 channels [y*32, y*32+32).
// ---------------------------------------------------------------------------
__global__ __launch_bounds__(64)
void reduce_v2e_half(const float4* __restrict__ x0, float4* __restrict__ x1) {
    const int tid  = threadIdx.x;
    const int e    = blockIdx.x * 2 + (tid >> 5);
    const int lane = tid & 31;
    const int c4   = blockIdx.y * 32 + lane;
    if (blockIdx.y == 0 && lane == 0) d_cnt_e[e] = 0;

    int beg = __ldg(&d_off_e[e]);
    int end = __ldg(&d_off_e[e + 1]);

    float4 s0 = make_float4(0.f, 0.f, 0.f, 0.f);
    float4 s1 = make_float4(0.f, 0.f, 0.f, 0.f);
    int j = beg;
    for (; j + 1 < end; j += 2) {
        int n0 = __ldg(&d_memb_e[j]);
        int n1 = __ldg(&d_memb_e[j + 1]);
        float4 v0 = __ldg(&x0[(size_t)n0 * C4 + c4]);
        float4 v1 = __ldg(&x0[(size_t)n1 * C4 + c4]);
        s0.x += v0.x; s0.y += v0.y; s0.z += v0.z; s0.w += v0.w;
        s1.x += v1.x; s1.y += v1.y; s1.z += v1.z; s1.w += v1.w;
    }
    if (j < end) {
        int n0 = __ldg(&d_memb_e[j]);
        float4 v0 = __ldg(&x0[(size_t)n0 * C4 + c4]);
        s0.x += v0.x; s0.y += v0.y; s0.z += v0.z; s0.w += v0.w;
    }
    s0.x += s1.x; s0.y += s1.y; s0.z += s1.z; s0.w += s1.w;
    x1[(size_t)e * C4 + c4] = s0;
}

// ---------------------------------------------------------------------------
// 5. reduce e2v (+x0, tf32-encode): g_m[n] = tf32(x0[n] + sum x1[e]).
// ---------------------------------------------------------------------------
__global__ __launch_bounds__(64)
void reduce_e2v(const float4* __restrict__ x0, const float4* __restrict__ x1) {
    const int n   = blockIdx.x;
    const int tid = threadIdx.x;
    int beg = d_off_n[n];
    int end = d_off_n[n + 1];
    if (tid == 0) d_cnt_n[n] = 0;

    float4 s0 = __ldg(&x0[(size_t)n * C4 + tid]);
    float4 s1 = make_float4(0.f, 0.f, 0.f, 0.f);
    int j = beg;
    for (; j + 1 < end; j += 2) {
        int e0 = __ldg(&d_memb_n[j]);
        int e1 = __ldg(&d_memb_n[j + 1]);
        float4 v0 = __ldg(&x1[(size_t)e0 * C4 + tid]);
        float4 v1 = __ldg(&x1[(size_t)e1 * C4 + tid]);
        s0.x += v0.x; s0.y += v0.y; s0.z += v0.z; s0.w += v0.w;
        s1.x += v1.x; s1.y += v1.y; s1.z += v1.z; s1.w += v1.w;
    }
    if (j < end) {
        int e0 = __ldg(&d_memb_n[j]);
        float4 v0 = __ldg(&x1[(size_t)e0 * C4 + tid]);
        s0.x += v0.x; s0.y += v0.y; s0.z += v0.z; s0.w += v0.w;
    }
    s0.x += s1.x; s0.y += s1.y; s0.z += s1.z; s0.w += s1.w;
    uint4 t;
    t.x = f2tf32(s0.x); t.y = f2tf32(s0.y); t.z = f2tf32(s0.z); t.w = f2tf32(s0.w);
    reinterpret_cast<uint4*>(g_m)[(size_t)n * C4 + tid] = t;
}

// ---------------------------------------------------------------------------
// 6. GEMM: out0 = g_m @ g_w^T + b — TF32 mma, BM=128 BN=256 GBK=16,
//    4-stage cp.async pipeline, fully unrolled k-loop, 1 sync/tile.
//    (R8 compute/staging mappings — conflict-free SPAD=20.)
// ---------------------------------------------------------------------------
#define GBM 128
#define GBK 16
#define SPAD 20
#define NTILES (C / GBK)
#define STAGES 4
#define A_WORDS (GBM * SPAD)
#define B_WORDS (256 * SPAD)

__device__ __forceinline__ void cp16(void* smem_dst, const void* gmem_src) {
    uint32_t s = (uint32_t)__cvta_generic_to_shared(smem_dst);
    asm volatile("cp.async.cg.shared.global [%0], [%1], 16;\n" :: "r"(s), "l"(gmem_src));
}
#define CP_COMMIT()   asm volatile("cp.async.commit_group;\n" ::: "memory")
#define CP_WAIT(n)    asm volatile("cp.async.wait_group %0;\n" :: "n"(n) : "memory")

__device__ __forceinline__ void mma_tf32_v(float c[4], const uint32_t a[4], const uint32_t b[2]) {
    asm volatile(
        "mma.sync.aligned.m16n8k8.row.col.f32.tf32.tf32.f32 "
        "{%0,%1,%2,%3}, {%4,%5,%6,%7}, {%8,%9}, {%0,%1,%2,%3};\n"
        : "+f"(c[0]), "+f"(c[1]), "+f"(c[2]), "+f"(c[3])
        : "r"(a[0]), "r"(a[1]), "r"(a[2]), "r"(a[3]), "r"(b[0]), "r"(b[1]));
}

__global__ __launch_bounds__(256, 1)
void gin_gemm_tf32(const float* __restrict__ bias,
                   float* __restrict__ out) {
    extern __shared__ uint32_t smem[];   // [STAGES][A_WORDS + B_WORDS]

    const int tid  = threadIdx.x;
    const int lane = tid & 31;
    const int wid  = tid >> 5;
    const int m_off = (wid >> 2) * 64;
    const int n_off = (wid & 3) * 64;
    const int m0 = blockIdx.x * GBM;

    // quad mappings (16B units) — conflict-free for SPAD=20
    const int a_row0 = tid >> 2;
    const int a_cq0  = (tid & 3) * 4;
    const int a_row1 = a_row0 + 64;
    const uint32_t* gm = reinterpret_cast<const uint32_t*>(g_m);
    const int b_row0 = tid >> 2;
    const int b_cq0  = (tid & 3) * 4;

    float acc[4][8][4];
    #pragma unroll
    for (int mf = 0; mf < 4; mf++)
        #pragma unroll
        for (int nf = 0; nf < 8; nf++)
            #pragma unroll
            for (int q = 0; q < 4; q++)
                acc[mf][nf][q] = 0.f;

    const int r  = lane >> 2;
    const int cq = lane & 3;

    auto issue_tile = [&](int t, int buf) {
        const int k0 = t * GBK;
        uint32_t* A = smem + buf * (A_WORDS + B_WORDS);
        uint32_t* B = A + A_WORDS;
        cp16(&A[a_row0 * SPAD + a_cq0], &gm[(size_t)(m0 + a_row0) * C + k0 + a_cq0]);
        cp16(&A[a_row1 * SPAD + a_cq0], &gm[(size_t)(m0 + a_row1) * C + k0 + a_cq0]);
        #pragma unroll
        for (int s = 0; s < 4; s++) {
            int row = b_row0 + s * 64;
            cp16(&B[row * SPAD + b_cq0], &g_w[(size_t)row * C + k0 + b_cq0]);
        }
        CP_COMMIT();
    };

    issue_tile(0, 0);
    issue_tile(1, 1);
    issue_tile(2, 2);

    #pragma unroll
    for (int t = 0; t < NTILES; t++) {
        // tile t must be complete; keep up to min(2, NTILES-1-t) groups pending
        if (t < NTILES - 2)      { CP_WAIT(2); }
        else if (t == NTILES - 2){ CP_WAIT(1); }
        else                     { CP_WAIT(0); }
        __syncthreads();
        if (t + 3 < NTILES) issue_tile(t + 3, (t + 3) % STAGES);

        uint32_t* A = smem + (t % STAGES) * (A_WORDS + B_WORDS);
        uint32_t* B = A + A_WORDS;

        #pragma unroll
        for (int ks = 0; ks < 2; ks++) {
            const int kk = ks * 8;
            uint32_t aF[4][4];
            #pragma unroll
            for (int mf = 0; mf < 4; mf++) {
                int row = m_off + mf * 16 + r;
                aF[mf][0] = A[row * SPAD + kk + cq];
                aF[mf][1] = A[(row + 8) * SPAD + kk + cq];
                aF[mf][2] = A[row * SPAD + kk + cq + 4];
                aF[mf][3] = A[(row + 8) * SPAD + kk + cq + 4];
            }
            #pragma unroll
            for (int nf = 0; nf < 8; nf++) {
                uint32_t bF[2];
                int col = n_off + nf * 8 + r;
                bF[0] = B[col * SPAD + kk + cq];
                bF[1] = B[col * SPAD + kk + cq + 4];
                #pragma unroll
                for (int mf = 0; mf < 4; mf++)
                    mma_tf32_v(acc[mf][nf], aF[mf], bF);
            }
        }
    }

    // ---- epilogue ----
    #pragma unroll
    for (int mf = 0; mf < 4; mf++) {
        #pragma unroll
        for (int nf = 0; nf < 8; nf++) {
            int gc = n_off + nf * 8 + cq * 2;
            float bb0 = bias[gc];
            float bb1 = bias[gc + 1];
            int gr = m0 + m_off + mf * 16 + r;
            if (gr < N_NODES) {
                float2 v = make_float2(acc[mf][nf][0] + bb0, acc[mf][nf][1] + bb1);
                *reinterpret_cast<float2*>(&out[(size_t)gr * C + gc]) = v;
            }
            if (gr + 8 < N_NODES) {
                float2 v = make_float2(acc[mf][nf][2] + bb0, acc[mf][nf][3] + bb1);
                *reinterpret_cast<float2*>(&out[(size_t)(gr + 8) * C + gc]) = v;
            }
        }
    }
}

#define GEMM_SMEM_BYTES (STAGES * (A_WORDS + B_WORDS) * 4)

// ---------------------------------------------------------------------------
// Launch
// ---------------------------------------------------------------------------
extern "C" void kernel_launch(void* const* d_in, const int* in_sizes, int n_in,
                              void* d_out, int out_size) {
    const float* x0       = (const float*)d_in[0];
    const int*   node_idx = (const int*)d_in[1];
    const int*   edge_idx = (const int*)d_in[2];
    const float* W        = (const float*)d_in[3];
    const float* b        = (const float*)d_in[4];

    float* out = (float*)d_out;
    float* x1  = out + (size_t)N_NODES * C;

    // CSR build + W conversion (counters pre-zeroed by previous replay)
    hist_kernel<<<800, 256>>>(node_idx, edge_idx,
                              reinterpret_cast<const float4*>(W));
    scan_two_kernel<<<2, 1024>>>();
    fill_kernel<<<800, 256>>>(node_idx, edge_idx);

    // v2e: two channel-half passes (L2-resident working set per pass)
    {
        dim3 grid(N_EDGES / 2, 2);
        reduce_v2e_half<<<grid, 64>>>(reinterpret_cast<const float4*>(x0),
                                      reinterpret_cast<float4*>(x1));
    }

    // e2v (+x0, tf32 encode)
    reduce_e2v<<<N_NODES, 64>>>(reinterpret_cast<const float4*>(x0),
                                reinterpret_cast<const float4*>(x1));

    // GEMM: out0 = g_m @ g_w^T + b
    {
        cudaFuncSetAttribute(gin_gemm_tf32,
                             cudaFuncAttributeMaxDynamicSharedMemorySize,
                             GEMM_SMEM_BYTES);
        int grid = (N_NODES + GBM - 1) / GBM;
        gin_gemm_tf32<<<grid, 256, GEMM_SMEM_BYTES>>>(b, out);
    }
}

// round 13
// speedup vs baseline: 1.3040x; 1.3040x over previous
#include <cuda_runtime.h>
#include <cstdint>

#define N_NODES 100000
#define N_NODES_PAD 100096   // padded so GEMM A-tile loads never go OOB
#define N_EDGES 50000
#define NNZ     800000
#define C       256
#define C4      (C / 4)   // 64 float4 per row

// ---------------- scratch (__device__ globals: allowed) ----------------
__device__ float    g_m[(size_t)N_NODES_PAD * C];  // tf32-encoded (x0 + m)
__device__ uint32_t g_w[(size_t)C * C];            // tf32-encoded W
__device__ int   d_cnt_e[N_EDGES];
__device__ int   d_cnt_n[N_NODES];
__device__ int   d_off_e[N_EDGES + 1];
__device__ int   d_off_n[N_NODES + 1];
__device__ int   d_memb_e[NNZ];                // node ids grouped by edge
__device__ int   d_memb_n[NNZ];                // edge ids grouped by node

__device__ __forceinline__ uint32_t f2tf32(float f) {
    uint32_t r;
    asm("cvt.rna.tf32.f32 %0, %1;" : "=r"(r) : "f"(f));
    return r;
}

// ---------------------------------------------------------------------------
// 1. histogram (grid-stride, R8 form) + W->tf32 conversion folded in
// ---------------------------------------------------------------------------
__global__ void hist_kernel(const int* __restrict__ node_idx,
                            const int* __restrict__ edge_idx,
                            const float4* __restrict__ W) {
    int idx = blockIdx.x * blockDim.x + threadIdx.x;

    // fold W conversion into the first 64 blocks (16384 uint4 total)
    if (idx < C * C / 4) {
        float4 v = W[idx];
        uint4 t;
        t.x = f2tf32(v.x); t.y = f2tf32(v.y); t.z = f2tf32(v.z); t.w = f2tf32(v.w);
        reinterpret_cast<uint4*>(g_w)[idx] = t;
    }

    int stride = gridDim.x * blockDim.x;
    for (int i = idx; i < NNZ; i += stride) {
        atomicAdd(&d_cnt_e[edge_idx[i]], 1);
        atomicAdd(&d_cnt_n[node_idx[i]], 1);
    }
}

// ---------------------------------------------------------------------------
// 2. exclusive scan, VT=4 (int4), R8 form. block 0 -> edges, block 1 -> nodes.
// ---------------------------------------------------------------------------
__global__ __launch_bounds__(1024)
void scan_two_kernel() {
    int* cnt;
    int* off;
    int  L;
    if (blockIdx.x == 0) { cnt = d_cnt_e; off = d_off_e; L = N_EDGES; }
    else                 { cnt = d_cnt_n; off = d_off_n; L = N_NODES; }

    const int tid  = threadIdx.x;
    const int lane = tid & 31;
    const int wid  = tid >> 5;
    __shared__ int warp_sum[32];

    const int L4 = L >> 2;
    int running = 0;
    for (int base4 = 0; base4 < L4; base4 += 1024) {
        int i4 = base4 + tid;
        int4 v = make_int4(0, 0, 0, 0);
        if (i4 < L4) v = reinterpret_cast<const int4*>(cnt)[i4];
        int p0 = v.x;
        int p1 = p0 + v.y;
        int p2 = p1 + v.z;
        int p3 = p2 + v.w;
        int tot = p3;
        int w = tot;
        #pragma unroll
        for (int d = 1; d < 32; d <<= 1) {
            int t = __shfl_up_sync(0xffffffffu, w, d);
            if (lane >= d) w += t;
        }
        if (lane == 31) warp_sum[wid] = w;
        __syncthreads();
        if (wid == 0) {
            int ws = warp_sum[lane];
            #pragma unroll
            for (int d = 1; d < 32; d <<= 1) {
                int t = __shfl_up_sync(0xffffffffu, ws, d);
                if (lane >= d) ws += t;
            }
            warp_sum[lane] = ws;
        }
        __syncthreads();
        int excl = (w - tot) + (wid > 0 ? warp_sum[wid - 1] : 0) + running;
        if (i4 < L4) {
            int i = i4 * 4;
            off[i + 1] = excl + p0;
            off[i + 2] = excl + p1;
            off[i + 3] = excl + p2;
            off[i + 4] = excl + p3;
        }
        running += warp_sum[31];
        __syncthreads();
    }
    if (tid == 0) off[0] = 0;
    for (int i = tid; i < L; i += 1024) cnt[i] = 0;
}

// ---------------------------------------------------------------------------
// 3. fill member lists (rank via int atomics)
// ---------------------------------------------------------------------------
__global__ void fill_kernel(const int* __restrict__ node_idx,
                            const int* __restrict__ edge_idx) {
    int idx = blockIdx.x * blockDim.x + threadIdx.x;
    int stride = gridDim.x * blockDim.x;
    for (int i = idx; i < NNZ; i += stride) {
        int n = node_idx[i];
        int e = edge_idx[i];
        int re = atomicAdd(&d_cnt_e[e], 1);
        d_memb_e[d_off_e[e] + re] = n;
        int rn = atomicAdd(&d_cnt_n[n], 1);
        d_memb_n[d_off_n[n] + rn] = e;
    }
}

// ---------------------------------------------------------------------------
// 4. reduce v2e, channel-split: pass y covers float4 channels [y*32, y*32+32).
// ---------------------------------------------------------------------------
__global__ __launch_bounds__(64)
void reduce_v2e_half(const float4* __restrict__ x0, float4* __restrict__ x1) {
    const int tid  = threadIdx.x;
    const int e    = blockIdx.x * 2 + (tid >> 5);
    const int lane = tid & 31;
    const int c4   = blockIdx.y * 32 + lane;
    if (blockIdx.y == 0 && lane == 0) d_cnt_e[e] = 0;

    int beg = __ldg(&d_off_e[e]);
    int end = __ldg(&d_off_e[e + 1]);

    float4 s0 = make_float4(0.f, 0.f, 0.f, 0.f);
    float4 s1 = make_float4(0.f, 0.f, 0.f, 0.f);
    int j = beg;
    for (; j + 1 < end; j += 2) {
        int n0 = __ldg(&d_memb_e[j]);
        int n1 = __ldg(&d_memb_e[j + 1]);
        float4 v0 = __ldg(&x0[(size_t)n0 * C4 + c4]);
        float4 v1 = __ldg(&x0[(size_t)n1 * C4 + c4]);
        s0.x += v0.x; s0.y += v0.y; s0.z += v0.z; s0.w += v0.w;
        s1.x += v1.x; s1.y += v1.y; s1.z += v1.z; s1.w += v1.w;
    }
    if (j < end) {
        int n0 = __ldg(&d_memb_e[j]);
        float4 v0 = __ldg(&x0[(size_t)n0 * C4 + c4]);
        s0.x += v0.x; s0.y += v0.y; s0.z += v0.z; s0.w += v0.w;
    }
    s0.x += s1.x; s0.y += s1.y; s0.z += s1.z; s0.w += s1.w;
    x1[(size_t)e * C4 + c4] = s0;
}

// ---------------------------------------------------------------------------
// 5. reduce e2v (+x0, tf32-encode): g_m[n] = tf32(x0[n] + sum x1[e]).
// ---------------------------------------------------------------------------
__global__ __launch_bounds__(64)
void reduce_e2v(const float4* __restrict__ x0, const float4* __restrict__ x1) {
    const int n   = blockIdx.x;
    const int tid = threadIdx.x;
    int beg = d_off_n[n];
    int end = d_off_n[n + 1];
    if (tid == 0) d_cnt_n[n] = 0;

    float4 s0 = __ldg(&x0[(size_t)n * C4 + tid]);
    float4 s1 = make_float4(0.f, 0.f, 0.f, 0.f);
    int j = beg;
    for (; j + 1 < end; j += 2) {
        int e0 = __ldg(&d_memb_n[j]);
        int e1 = __ldg(&d_memb_n[j + 1]);
        float4 v0 = __ldg(&x1[(size_t)e0 * C4 + tid]);
        float4 v1 = __ldg(&x1[(size_t)e1 * C4 + tid]);
        s0.x += v0.x; s0.y += v0.y; s0.z += v0.z; s0.w += v0.w;
        s1.x += v1.x; s1.y += v1.y; s1.z += v1.z; s1.w += v1.w;
    }
    if (j < end) {
        int e0 = __ldg(&d_memb_n[j]);
        float4 v0 = __ldg(&x1[(size_t)e0 * C4 + tid]);
        s0.x += v0.x; s0.y += v0.y; s0.z += v0.z; s0.w += v0.w;
    }
    s0.x += s1.x; s0.y += s1.y; s0.z += s1.z; s0.w += s1.w;
    uint4 t;
    t.x = f2tf32(s0.x); t.y = f2tf32(s0.y); t.z = f2tf32(s0.z); t.w = f2tf32(s0.w);
    reinterpret_cast<uint4*>(g_m)[(size_t)n * C4 + tid] = t;
}

// ---------------------------------------------------------------------------
// 6. GEMM: out0 = g_m @ g_w^T + b — TF32 mma, BM=128 BN=256 GBK=16,
//    3-stage cp.async pipeline, ONE __syncthreads per k-tile.
//    (EXACT R8 champion configuration — conflict-free SPAD=20 staging,
//     `#pragma unroll 1` outer loop.)
// ---------------------------------------------------------------------------
#define GBM 128
#define GBK 16
#define SPAD 20
#define NTILES (C / GBK)
#define STAGES 3
#define A_WORDS (GBM * SPAD)
#define B_WORDS (256 * SPAD)

__device__ __forceinline__ void cp16(void* smem_dst, const void* gmem_src) {
    uint32_t s = (uint32_t)__cvta_generic_to_shared(smem_dst);
    asm volatile("cp.async.cg.shared.global [%0], [%1], 16;\n" :: "r"(s), "l"(gmem_src));
}
#define CP_COMMIT()   asm volatile("cp.async.commit_group;\n" ::: "memory")
#define CP_WAIT(n)    asm volatile("cp.async.wait_group %0;\n" :: "n"(n) : "memory")

__device__ __forceinline__ void mma_tf32_v(float c[4], const uint32_t a[4], const uint32_t b[2]) {
    asm volatile(
        "mma.sync.aligned.m16n8k8.row.col.f32.tf32.tf32.f32 "
        "{%0,%1,%2,%3}, {%4,%5,%6,%7}, {%8,%9}, {%0,%1,%2,%3};\n"
        : "+f"(c[0]), "+f"(c[1]), "+f"(c[2]), "+f"(c[3])
        : "r"(a[0]), "r"(a[1]), "r"(a[2]), "r"(a[3]), "r"(b[0]), "r"(b[1]));
}

__global__ __launch_bounds__(256, 1)
void gin_gemm_tf32(const float* __restrict__ bias,
                   float* __restrict__ out) {
    extern __shared__ uint32_t smem[];   // [STAGES][A_WORDS + B_WORDS]

    const int tid  = threadIdx.x;
    const int lane = tid & 31;
    const int wid  = tid >> 5;
    const int m_off = (wid >> 2) * 64;
    const int n_off = (wid & 3) * 64;
    const int m0 = blockIdx.x * GBM;

    // quad mappings (16B units) — conflict-free for SPAD=20
    const int a_row0 = tid >> 2;
    const int a_cq0  = (tid & 3) * 4;
    const int a_row1 = a_row0 + 64;
    const uint32_t* gm = reinterpret_cast<const uint32_t*>(g_m);
    const int b_row0 = tid >> 2;
    const int b_cq0  = (tid & 3) * 4;

    float acc[4][8][4];
    #pragma unroll
    for (int mf = 0; mf < 4; mf++)
        #pragma unroll
        for (int nf = 0; nf < 8; nf++)
            #pragma unroll
            for (int q = 0; q < 4; q++)
                acc[mf][nf][q] = 0.f;

    const int r  = lane >> 2;
    const int cq = lane & 3;

    auto issue_tile = [&](int t, int buf) {
        const int k0 = t * GBK;
        uint32_t* A = smem + buf * (A_WORDS + B_WORDS);
        uint32_t* B = A + A_WORDS;
        cp16(&A[a_row0 * SPAD + a_cq0], &gm[(size_t)(m0 + a_row0) * C + k0 + a_cq0]);
        cp16(&A[a_row1 * SPAD + a_cq0], &gm[(size_t)(m0 + a_row1) * C + k0 + a_cq0]);
        #pragma unroll
        for (int s = 0; s < 4; s++) {
            int row = b_row0 + s * 64;
            cp16(&B[row * SPAD + b_cq0], &g_w[(size_t)row * C + k0 + b_cq0]);
        }
        CP_COMMIT();
    };

    issue_tile(0, 0);
    issue_tile(1, 1);

    #pragma unroll 1
    for (int t = 0; t < NTILES; t++) {
        if (t + 1 < NTILES) { CP_WAIT(1); } else { CP_WAIT(0); }
        __syncthreads();
        if (t + 2 < NTILES) issue_tile(t + 2, (t + 2) % STAGES);

        uint32_t* A = smem + (t % STAGES) * (A_WORDS + B_WORDS);
        uint32_t* B = A + A_WORDS;

        #pragma unroll
        for (int ks = 0; ks < 2; ks++) {
            const int kk = ks * 8;
            uint32_t aF[4][4];
            #pragma unroll
            for (int mf = 0; mf < 4; mf++) {
                int row = m_off + mf * 16 + r;
                aF[mf][0] = A[row * SPAD + kk + cq];
                aF[mf][1] = A[(row + 8) * SPAD + kk + cq];
                aF[mf][2] = A[row * SPAD + kk + cq + 4];
                aF[mf][3] = A[(row + 8) * SPAD + kk + cq + 4];
            }
            #pragma unroll
            for (int nf = 0; nf < 8; nf++) {
                uint32_t bF[2];
                int col = n_off + nf * 8 + r;
                bF[0] = B[col * SPAD + kk + cq];
                bF[1] = B[col * SPAD + kk + cq + 4];
                #pragma unroll
                for (int mf = 0; mf < 4; mf++)
                    mma_tf32_v(acc[mf][nf], aF[mf], bF);
            }
        }
    }

    // ---- epilogue ----
    #pragma unroll
    for (int mf = 0; mf < 4; mf++) {
        #pragma unroll
        for (int nf = 0; nf < 8; nf++) {
            int gc = n_off + nf * 8 + cq * 2;
            float bb0 = bias[gc];
            float bb1 = bias[gc + 1];
            int gr = m0 + m_off + mf * 16 + r;
            if (gr < N_NODES) {
                float2 v = make_float2(acc[mf][nf][0] + bb0, acc[mf][nf][1] + bb1);
                *reinterpret_cast<float2*>(&out[(size_t)gr * C + gc]) = v;
            }
            if (gr + 8 < N_NODES) {
                float2 v = make_float2(acc[mf][nf][2] + bb0, acc[mf][nf][3] + bb1);
                *reinterpret_cast<float2*>(&out[(size_t)(gr + 8) * C + gc]) = v;
            }
        }
    }
}

#define GEMM_SMEM_BYTES (STAGES * (A_WORDS + B_WORDS) * 4)

// ---------------------------------------------------------------------------
// Launch
// ---------------------------------------------------------------------------
extern "C" void kernel_launch(void* const* d_in, const int* in_sizes, int n_in,
                              void* d_out, int out_size) {
    const float* x0       = (const float*)d_in[0];
    const int*   node_idx = (const int*)d_in[1];
    const int*   edge_idx = (const int*)d_in[2];
    const float* W        = (const float*)d_in[3];
    const float* b        = (const float*)d_in[4];

    float* out = (float*)d_out;
    float* x1  = out + (size_t)N_NODES * C;

    // CSR build + W conversion (counters pre-zeroed by previous replay)
    hist_kernel<<<800, 256>>>(node_idx, edge_idx,
                              reinterpret_cast<const float4*>(W));
    scan_two_kernel<<<2, 1024>>>();
    fill_kernel<<<800, 256>>>(node_idx, edge_idx);

    // v2e: two channel-half passes (L2-resident working set per pass)
    {
        dim3 grid(N_EDGES / 2, 2);
        reduce_v2e_half<<<grid, 64>>>(reinterpret_cast<const float4*>(x0),
                                      reinterpret_cast<float4*>(x1));
    }

    // e2v (+x0, tf32 encode)
    reduce_e2v<<<N_NODES, 64>>>(reinterpret_cast<const float4*>(x0),
                                reinterpret_cast<const float4*>(x1));

    // GEMM: out0 = g_m @ g_w^T + b
    {
        cudaFuncSetAttribute(gin_gemm_tf32,
                             cudaFuncAttributeMaxDynamicSharedMemorySize,
                             GEMM_SMEM_BYTES);
        int grid = (N_NODES + GBM - 1) / GBM;
        gin_gemm_tf32<<<grid, 256, GEMM_SMEM_BYTES>>>(b, out);
    }
}

// round 14
// speedup vs baseline: 1.4027x; 1.0756x over previous
#include <cuda_runtime.h>
#include <cstdint>

#define N_NODES 100000
#define N_NODES_PAD 100096   // padded so GEMM A-tile loads never go OOB
#define N_EDGES 50000
#define NNZ     800000
#define C       256
#define C4      (C / 4)   // 64 float4 per row

// ---------------- scratch (__device__ globals: allowed) ----------------
__device__ float    g_m[(size_t)N_NODES_PAD * C];  // tf32-encoded (x0 + m)
__device__ uint32_t g_w[(size_t)C * C];            // tf32-encoded W
__device__ int   d_cnt_e[N_EDGES];
__device__ int   d_cnt_n[N_NODES];
__device__ int   d_off_e[N_EDGES + 1];
__device__ int   d_off_n[N_NODES + 1];
__device__ int   d_memb_e[NNZ];                // node ids grouped by edge
__device__ int   d_memb_n[NNZ];                // edge ids grouped by node

__device__ __forceinline__ uint32_t f2tf32(float f) {
    uint32_t r;
    asm("cvt.rna.tf32.f32 %0, %1;" : "=r"(r) : "f"(f));
    return r;
}

// ---------------------------------------------------------------------------
// 1a. edge-side histogram (counts only edge_idx)
// ---------------------------------------------------------------------------
__global__ void hist_e_kernel(const int* __restrict__ edge_idx) {
    int idx = blockIdx.x * blockDim.x + threadIdx.x;
    int stride = gridDim.x * blockDim.x;
    for (int i = idx; i < NNZ; i += stride)
        atomicAdd(&d_cnt_e[edge_idx[i]], 1);
}

// ---------------------------------------------------------------------------
// 1b. node-side histogram + W->tf32 conversion folded in
// ---------------------------------------------------------------------------
__global__ void hist_n_kernel(const int* __restrict__ node_idx,
                              const float4* __restrict__ W) {
    int idx = blockIdx.x * blockDim.x + threadIdx.x;

    if (idx < C * C / 4) {
        float4 v = W[idx];
        uint4 t;
        t.x = f2tf32(v.x); t.y = f2tf32(v.y); t.z = f2tf32(v.z); t.w = f2tf32(v.w);
        reinterpret_cast<uint4*>(g_w)[idx] = t;
    }

    int stride = gridDim.x * blockDim.x;
    for (int i = idx; i < NNZ; i += stride)
        atomicAdd(&d_cnt_n[node_idx[i]], 1);
}

// ---------------------------------------------------------------------------
// 2. exclusive scan, VT=4 (int4) — one side per launch (which: 0=edge, 1=node)
//    Re-zeroes counts (reused as rank counters by fill).
// ---------------------------------------------------------------------------
__global__ __launch_bounds__(1024)
void scan_one_kernel(int which) {
    int* cnt;
    int* off;
    int  L;
    if (which == 0) { cnt = d_cnt_e; off = d_off_e; L = N_EDGES; }
    else            { cnt = d_cnt_n; off = d_off_n; L = N_NODES; }

    const int tid  = threadIdx.x;
    const int lane = tid & 31;
    const int wid  = tid >> 5;
    __shared__ int warp_sum[32];

    const int L4 = L >> 2;
    int running = 0;
    for (int base4 = 0; base4 < L4; base4 += 1024) {
        int i4 = base4 + tid;
        int4 v = make_int4(0, 0, 0, 0);
        if (i4 < L4) v = reinterpret_cast<const int4*>(cnt)[i4];
        int p0 = v.x;
        int p1 = p0 + v.y;
        int p2 = p1 + v.z;
        int p3 = p2 + v.w;
        int tot = p3;
        int w = tot;
        #pragma unroll
        for (int d = 1; d < 32; d <<= 1) {
            int t = __shfl_up_sync(0xffffffffu, w, d);
            if (lane >= d) w += t;
        }
        if (lane == 31) warp_sum[wid] = w;
        __syncthreads();
        if (wid == 0) {
            int ws = warp_sum[lane];
            #pragma unroll
            for (int d = 1; d < 32; d <<= 1) {
                int t = __shfl_up_sync(0xffffffffu, ws, d);
                if (lane >= d) ws += t;
            }
            warp_sum[lane] = ws;
        }
        __syncthreads();
        int excl = (w - tot) + (wid > 0 ? warp_sum[wid - 1] : 0) + running;
        if (i4 < L4) {
            int i = i4 * 4;
            off[i + 1] = excl + p0;
            off[i + 2] = excl + p1;
            off[i + 3] = excl + p2;
            off[i + 4] = excl + p3;
        }
        running += warp_sum[31];
        __syncthreads();
    }
    if (tid == 0) off[0] = 0;
    for (int i = tid; i < L; i += 1024) cnt[i] = 0;
}

// ---------------------------------------------------------------------------
// 3a. fill edge-side member list
// ---------------------------------------------------------------------------
__global__ void fill_e_kernel(const int* __restrict__ node_idx,
                              const int* __restrict__ edge_idx) {
    int idx = blockIdx.x * blockDim.x + threadIdx.x;
    int stride = gridDim.x * blockDim.x;
    for (int i = idx; i < NNZ; i += stride) {
        int n = node_idx[i];
        int e = edge_idx[i];
        int re = atomicAdd(&d_cnt_e[e], 1);
        d_memb_e[d_off_e[e] + re] = n;
    }
}

// ---------------------------------------------------------------------------
// 3b. fill node-side member list
// ---------------------------------------------------------------------------
__global__ void fill_n_kernel(const int* __restrict__ node_idx,
                              const int* __restrict__ edge_idx) {
    int idx = blockIdx.x * blockDim.x + threadIdx.x;
    int stride = gridDim.x * blockDim.x;
    for (int i = idx; i < NNZ; i += stride) {
        int n = node_idx[i];
        int e = edge_idx[i];
        int rn = atomicAdd(&d_cnt_n[n], 1);
        d_memb_n[d_off_n[n] + rn] = e;
    }
}

// ---------------------------------------------------------------------------
// 4. reduce v2e, channel-split (champion form). Zeroes d_cnt_e in pass 0.
// ---------------------------------------------------------------------------
__global__ __launch_bounds__(64)
void reduce_v2e_half(const float4* __restrict__ x0, float4* __restrict__ x1) {
    const int tid  = threadIdx.x;
    const int e    = blockIdx.x * 2 + (tid >> 5);
    const int lane = tid & 31;
    const int c4   = blockIdx.y * 32 + lane;
    if (blockIdx.y == 0 && lane == 0) d_cnt_e[e] = 0;

    int beg = __ldg(&d_off_e[e]);
    int end = __ldg(&d_off_e[e + 1]);

    float4 s0 = make_float4(0.f, 0.f, 0.f, 0.f);
    float4 s1 = make_float4(0.f, 0.f, 0.f, 0.f);
    int j = beg;
    for (; j + 1 < end; j += 2) {
        int n0 = __ldg(&d_memb_e[j]);
        int n1 = __ldg(&d_memb_e[j + 1]);
        float4 v0 = __ldg(&x0[(size_t)n0 * C4 + c4]);
        float4 v1 = __ldg(&x0[(size_t)n1 * C4 + c4]);
        s0.x += v0.x; s0.y += v0.y; s0.z += v0.z; s0.w += v0.w;
        s1.x += v1.x; s1.y += v1.y; s1.z += v1.z; s1.w += v1.w;
    }
    if (j < end) {
        int n0 = __ldg(&d_memb_e[j]);
        float4 v0 = __ldg(&x0[(size_t)n0 * C4 + c4]);
        s0.x += v0.x; s0.y += v0.y; s0.z += v0.z; s0.w += v0.w;
    }
    s0.x += s1.x; s0.y += s1.y; s0.z += s1.z; s0.w += s1.w;
    x1[(size_t)e * C4 + c4] = s0;
}

// ---------------------------------------------------------------------------
// 5. reduce e2v (+x0, tf32-encode, champion form). Zeroes d_cnt_n.
// ---------------------------------------------------------------------------
__global__ __launch_bounds__(64)
void reduce_e2v(const float4* __restrict__ x0, const float4* __restrict__ x1) {
    const int n   = blockIdx.x;
    const int tid = threadIdx.x;
    int beg = d_off_n[n];
    int end = d_off_n[n + 1];
    if (tid == 0) d_cnt_n[n] = 0;

    float4 s0 = __ldg(&x0[(size_t)n * C4 + tid]);
    float4 s1 = make_float4(0.f, 0.f, 0.f, 0.f);
    int j = beg;
    for (; j + 1 < end; j += 2) {
        int e0 = __ldg(&d_memb_n[j]);
        int e1 = __ldg(&d_memb_n[j + 1]);
        float4 v0 = __ldg(&x1[(size_t)e0 * C4 + tid]);
        float4 v1 = __ldg(&x1[(size_t)e1 * C4 + tid]);
        s0.x += v0.x; s0.y += v0.y; s0.z += v0.z; s0.w += v0.w;
        s1.x += v1.x; s1.y += v1.y; s1.z += v1.z; s1.w += v1.w;
    }
    if (j < end) {
        int e0 = __ldg(&d_memb_n[j]);
        float4 v0 = __ldg(&x1[(size_t)e0 * C4 + tid]);
        s0.x += v0.x; s0.y += v0.y; s0.z += v0.z; s0.w += v0.w;
    }
    s0.x += s1.x; s0.y += s1.y; s0.z += s1.z; s0.w += s1.w;
    uint4 t;
    t.x = f2tf32(s0.x); t.y = f2tf32(s0.y); t.z = f2tf32(s0.z); t.w = f2tf32(s0.w);
    reinterpret_cast<uint4*>(g_m)[(size_t)n * C4 + tid] = t;
}

// ---------------------------------------------------------------------------
// 6. GEMM (EXACT champion): TF32 mma, BM=128 BN=256 GBK=16, 3-stage cp.async,
//    one __syncthreads per k-tile, conflict-free SPAD=20, `unroll 1` loop.
// ---------------------------------------------------------------------------
#define GBM 128
#define GBK 16
#define SPAD 20
#define NTILES (C / GBK)
#define STAGES 3
#define A_WORDS (GBM * SPAD)
#define B_WORDS (256 * SPAD)

__device__ __forceinline__ void cp16(void* smem_dst, const void* gmem_src) {
    uint32_t s = (uint32_t)__cvta_generic_to_shared(smem_dst);
    asm volatile("cp.async.cg.shared.global [%0], [%1], 16;\n" :: "r"(s), "l"(gmem_src));
}
#define CP_COMMIT()   asm volatile("cp.async.commit_group;\n" ::: "memory")
#define CP_WAIT(n)    asm volatile("cp.async.wait_group %0;\n" :: "n"(n) : "memory")

__device__ __forceinline__ void mma_tf32_v(float c[4], const uint32_t a[4], const uint32_t b[2]) {
    asm volatile(
        "mma.sync.aligned.m16n8k8.row.col.f32.tf32.tf32.f32 "
        "{%0,%1,%2,%3}, {%4,%5,%6,%7}, {%8,%9}, {%0,%1,%2,%3};\n"
        : "+f"(c[0]), "+f"(c[1]), "+f"(c[2]), "+f"(c[3])
        : "r"(a[0]), "r"(a[1]), "r"(a[2]), "r"(a[3]), "r"(b[0]), "r"(b[1]));
}

__global__ __launch_bounds__(256, 1)
void gin_gemm_tf32(const float* __restrict__ bias,
                   float* __restrict__ out) {
    extern __shared__ uint32_t smem[];   // [STAGES][A_WORDS + B_WORDS]

    const int tid  = threadIdx.x;
    const int lane = tid & 31;
    const int wid  = tid >> 5;
    const int m_off = (wid >> 2) * 64;
    const int n_off = (wid & 3) * 64;
    const int m0 = blockIdx.x * GBM;

    const int a_row0 = tid >> 2;
    const int a_cq0  = (tid & 3) * 4;
    const int a_row1 = a_row0 + 64;
    const uint32_t* gm = reinterpret_cast<const uint32_t*>(g_m);
    const int b_row0 = tid >> 2;
    const int b_cq0  = (tid & 3) * 4;

    float acc[4][8][4];
    #pragma unroll
    for (int mf = 0; mf < 4; mf++)
        #pragma unroll
        for (int nf = 0; nf < 8; nf++)
            #pragma unroll
            for (int q = 0; q < 4; q++)
                acc[mf][nf][q] = 0.f;

    const int r  = lane >> 2;
    const int cq = lane & 3;

    auto issue_tile = [&](int t, int buf) {
        const int k0 = t * GBK;
        uint32_t* A = smem + buf * (A_WORDS + B_WORDS);
        uint32_t* B = A + A_WORDS;
        cp16(&A[a_row0 * SPAD + a_cq0], &gm[(size_t)(m0 + a_row0) * C + k0 + a_cq0]);
        cp16(&A[a_row1 * SPAD + a_cq0], &gm[(size_t)(m0 + a_row1) * C + k0 + a_cq0]);
        #pragma unroll
        for (int s = 0; s < 4; s++) {
            int row = b_row0 + s * 64;
            cp16(&B[row * SPAD + b_cq0], &g_w[(size_t)row * C + k0 + b_cq0]);
        }
        CP_COMMIT();
    };

    issue_tile(0, 0);
    issue_tile(1, 1);

    #pragma unroll 1
    for (int t = 0; t < NTILES; t++) {
        if (t + 1 < NTILES) { CP_WAIT(1); } else { CP_WAIT(0); }
        __syncthreads();
        if (t + 2 < NTILES) issue_tile(t + 2, (t + 2) % STAGES);

        uint32_t* A = smem + (t % STAGES) * (A_WORDS + B_WORDS);
        uint32_t* B = A + A_WORDS;

        #pragma unroll
        for (int ks = 0; ks < 2; ks++) {
            const int kk = ks * 8;
            uint32_t aF[4][4];
            #pragma unroll
            for (int mf = 0; mf < 4; mf++) {
                int row = m_off + mf * 16 + r;
                aF[mf][0] = A[row * SPAD + kk + cq];
                aF[mf][1] = A[(row + 8) * SPAD + kk + cq];
                aF[mf][2] = A[row * SPAD + kk + cq + 4];
                aF[mf][3] = A[(row + 8) * SPAD + kk + cq + 4];
            }
            #pragma unroll
            for (int nf = 0; nf < 8; nf++) {
                uint32_t bF[2];
                int col = n_off + nf * 8 + r;
                bF[0] = B[col * SPAD + kk + cq];
                bF[1] = B[col * SPAD + kk + cq + 4];
                #pragma unroll
                for (int mf = 0; mf < 4; mf++)
                    mma_tf32_v(acc[mf][nf], aF[mf], bF);
            }
        }
    }

    #pragma unroll
    for (int mf = 0; mf < 4; mf++) {
        #pragma unroll
        for (int nf = 0; nf < 8; nf++) {
            int gc = n_off + nf * 8 + cq * 2;
            float bb0 = bias[gc];
            float bb1 = bias[gc + 1];
            int gr = m0 + m_off + mf * 16 + r;
            if (gr < N_NODES) {
                float2 v = make_float2(acc[mf][nf][0] + bb0, acc[mf][nf][1] + bb1);
                *reinterpret_cast<float2*>(&out[(size_t)gr * C + gc]) = v;
            }
            if (gr + 8 < N_NODES) {
                float2 v = make_float2(acc[mf][nf][2] + bb0, acc[mf][nf][3] + bb1);
                *reinterpret_cast<float2*>(&out[(size_t)(gr + 8) * C + gc]) = v;
            }
        }
    }
}

#define GEMM_SMEM_BYTES (STAGES * (A_WORDS + B_WORDS) * 4)

// ---------------------------------------------------------------------------
// Launch: fork node-side CSR chain onto a second stream (graph branch),
// join before e2v. Handles created once on the (uncaptured) correctness call.
// ---------------------------------------------------------------------------
extern "C" void kernel_launch(void* const* d_in, const int* in_sizes, int n_in,
                              void* d_out, int out_size) {
    const float* x0       = (const float*)d_in[0];
    const int*   node_idx = (const int*)d_in[1];
    const int*   edge_idx = (const int*)d_in[2];
    const float* W        = (const float*)d_in[3];
    const float* b        = (const float*)d_in[4];

    float* out = (float*)d_out;
    float* x1  = out + (size_t)N_NODES * C;

    static cudaStream_t s2 = nullptr;
    static cudaEvent_t  evFork = nullptr, evJoin = nullptr;
    if (s2 == nullptr) {
        cudaStreamCreateWithFlags(&s2, cudaStreamNonBlocking);
        cudaEventCreateWithFlags(&evFork, cudaEventDisableTiming);
        cudaEventCreateWithFlags(&evJoin, cudaEventDisableTiming);
    }

    // ---- fork: node-side chain on s2 ----
    cudaEventRecord(evFork, 0);
    cudaStreamWaitEvent(s2, evFork, 0);
    hist_n_kernel<<<800, 256, 0, s2>>>(node_idx,
                                       reinterpret_cast<const float4*>(W));
    scan_one_kernel<<<1, 1024, 0, s2>>>(1);
    fill_n_kernel<<<800, 256, 0, s2>>>(node_idx, edge_idx);
    cudaEventRecord(evJoin, s2);

    // ---- edge-side chain on default stream ----
    hist_e_kernel<<<800, 256>>>(edge_idx);
    scan_one_kernel<<<1, 1024>>>(0);
    fill_e_kernel<<<800, 256>>>(node_idx, edge_idx);
    {
        dim3 grid(N_EDGES / 2, 2);
        reduce_v2e_half<<<grid, 64>>>(reinterpret_cast<const float4*>(x0),
                                      reinterpret_cast<float4*>(x1));
    }

    // ---- join, then e2v + GEMM ----
    cudaStreamWaitEvent(0, evJoin, 0);
    reduce_e2v<<<N_NODES, 64>>>(reinterpret_cast<const float4*>(x0),
                                reinterpret_cast<const float4*>(x1));

    {
        cudaFuncSetAttribute(gin_gemm_tf32,
                             cudaFuncAttributeMaxDynamicSharedMemorySize,
                             GEMM_SMEM_BYTES);
        int grid = (N_NODES + GBM - 1) / GBM;
        gin_gemm_tf32<<<grid, 256, GEMM_SMEM_BYTES>>>(b, out);
    }
}

// round 15
// speedup vs baseline: 1.4051x; 1.0018x over previous
#include <cuda_runtime.h>
#include <cstdint>

#define N_NODES 100000
#define N_NODES_PAD 100096   // padded so GEMM A-tile loads never go OOB
#define N_EDGES 50000
#define NNZ     800000
#define C       256
#define C4      (C / 4)   // 64 float4 per row
#define N_HALF  50048     // 391 * 128, node split point

// ---------------- scratch (__device__ globals: allowed) ----------------
__device__ float    g_m[(size_t)N_NODES_PAD * C];  // tf32-encoded (x0 + m)
__device__ uint32_t g_w[(size_t)C * C];            // tf32-encoded W
__device__ int   d_cnt_e[N_EDGES];
__device__ int   d_cnt_n[N_NODES];
__device__ int   d_off_e[N_EDGES + 1];
__device__ int   d_off_n[N_NODES + 1];
__device__ int   d_memb_e[NNZ];                // node ids grouped by edge
__device__ int   d_memb_n[NNZ];                // edge ids grouped by node

__device__ __forceinline__ uint32_t f2tf32(float f) {
    uint32_t r;
    asm("cvt.rna.tf32.f32 %0, %1;" : "=r"(r) : "f"(f));
    return r;
}

// ---------------------------------------------------------------------------
// 1a. edge-side histogram (counts only edge_idx)
// ---------------------------------------------------------------------------
__global__ void hist_e_kernel(const int* __restrict__ edge_idx) {
    int idx = blockIdx.x * blockDim.x + threadIdx.x;
    int stride = gridDim.x * blockDim.x;
    for (int i = idx; i < NNZ; i += stride)
        atomicAdd(&d_cnt_e[edge_idx[i]], 1);
}

// ---------------------------------------------------------------------------
// 1b. node-side histogram + W->tf32 conversion folded in
// ---------------------------------------------------------------------------
__global__ void hist_n_kernel(const int* __restrict__ node_idx,
                              const float4* __restrict__ W) {
    int idx = blockIdx.x * blockDim.x + threadIdx.x;

    if (idx < C * C / 4) {
        float4 v = W[idx];
        uint4 t;
        t.x = f2tf32(v.x); t.y = f2tf32(v.y); t.z = f2tf32(v.z); t.w = f2tf32(v.w);
        reinterpret_cast<uint4*>(g_w)[idx] = t;
    }

    int stride = gridDim.x * blockDim.x;
    for (int i = idx; i < NNZ; i += stride)
        atomicAdd(&d_cnt_n[node_idx[i]], 1);
}

// ---------------------------------------------------------------------------
// 2. exclusive scan, VT=4 (int4) — one side per launch (which: 0=edge, 1=node)
// ---------------------------------------------------------------------------
__global__ __launch_bounds__(1024)
void scan_one_kernel(int which) {
    int* cnt;
    int* off;
    int  L;
    if (which == 0) { cnt = d_cnt_e; off = d_off_e; L = N_EDGES; }
    else            { cnt = d_cnt_n; off = d_off_n; L = N_NODES; }

    const int tid  = threadIdx.x;
    const int lane = tid & 31;
    const int wid  = tid >> 5;
    __shared__ int warp_sum[32];

    const int L4 = L >> 2;
    int running = 0;
    for (int base4 = 0; base4 < L4; base4 += 1024) {
        int i4 = base4 + tid;
        int4 v = make_int4(0, 0, 0, 0);
        if (i4 < L4) v = reinterpret_cast<const int4*>(cnt)[i4];
        int p0 = v.x;
        int p1 = p0 + v.y;
        int p2 = p1 + v.z;
        int p3 = p2 + v.w;
        int tot = p3;
        int w = tot;
        #pragma unroll
        for (int d = 1; d < 32; d <<= 1) {
            int t = __shfl_up_sync(0xffffffffu, w, d);
            if (lane >= d) w += t;
        }
        if (lane == 31) warp_sum[wid] = w;
        __syncthreads();
        if (wid == 0) {
            int ws = warp_sum[lane];
            #pragma unroll
            for (int d = 1; d < 32; d <<= 1) {
                int t = __shfl_up_sync(0xffffffffu, ws, d);
                if (lane >= d) ws += t;
            }
            warp_sum[lane] = ws;
        }
        __syncthreads();
        int excl = (w - tot) + (wid > 0 ? warp_sum[wid - 1] : 0) + running;
        if (i4 < L4) {
            int i = i4 * 4;
            off[i + 1] = excl + p0;
            off[i + 2] = excl + p1;
            off[i + 3] = excl + p2;
            off[i + 4] = excl + p3;
        }
        running += warp_sum[31];
        __syncthreads();
    }
    if (tid == 0) off[0] = 0;
    for (int i = tid; i < L; i += 1024) cnt[i] = 0;
}

// ---------------------------------------------------------------------------
// 3a. fill edge-side member list
// ---------------------------------------------------------------------------
__global__ void fill_e_kernel(const int* __restrict__ node_idx,
                              const int* __restrict__ edge_idx) {
    int idx = blockIdx.x * blockDim.x + threadIdx.x;
    int stride = gridDim.x * blockDim.x;
    for (int i = idx; i < NNZ; i += stride) {
        int n = node_idx[i];
        int e = edge_idx[i];
        int re = atomicAdd(&d_cnt_e[e], 1);
        d_memb_e[d_off_e[e] + re] = n;
    }
}

// ---------------------------------------------------------------------------
// 3b. fill node-side member list
// ---------------------------------------------------------------------------
__global__ void fill_n_kernel(const int* __restrict__ node_idx,
                              const int* __restrict__ edge_idx) {
    int idx = blockIdx.x * blockDim.x + threadIdx.x;
    int stride = gridDim.x * blockDim.x;
    for (int i = idx; i < NNZ; i += stride) {
        int n = node_idx[i];
        int e = edge_idx[i];
        int rn = atomicAdd(&d_cnt_n[n], 1);
        d_memb_n[d_off_n[n] + rn] = e;
    }
}

// ---------------------------------------------------------------------------
// 4. reduce v2e, channel-split (champion form). Zeroes d_cnt_e in pass 0.
// ---------------------------------------------------------------------------
__global__ __launch_bounds__(64)
void reduce_v2e_half(const float4* __restrict__ x0, float4* __restrict__ x1) {
    const int tid  = threadIdx.x;
    const int e    = blockIdx.x * 2 + (tid >> 5);
    const int lane = tid & 31;
    const int c4   = blockIdx.y * 32 + lane;
    if (blockIdx.y == 0 && lane == 0) d_cnt_e[e] = 0;

    int beg = __ldg(&d_off_e[e]);
    int end = __ldg(&d_off_e[e + 1]);

    float4 s0 = make_float4(0.f, 0.f, 0.f, 0.f);
    float4 s1 = make_float4(0.f, 0.f, 0.f, 0.f);
    int j = beg;
    for (; j + 1 < end; j += 2) {
        int n0 = __ldg(&d_memb_e[j]);
        int n1 = __ldg(&d_memb_e[j + 1]);
        float4 v0 = __ldg(&x0[(size_t)n0 * C4 + c4]);
        float4 v1 = __ldg(&x0[(size_t)n1 * C4 + c4]);
        s0.x += v0.x; s0.y += v0.y; s0.z += v0.z; s0.w += v0.w;
        s1.x += v1.x; s1.y += v1.y; s1.z += v1.z; s1.w += v1.w;
    }
    if (j < end) {
        int n0 = __ldg(&d_memb_e[j]);
        float4 v0 = __ldg(&x0[(size_t)n0 * C4 + c4]);
        s0.x += v0.x; s0.y += v0.y; s0.z += v0.z; s0.w += v0.w;
    }
    s0.x += s1.x; s0.y += s1.y; s0.z += s1.z; s0.w += s1.w;
    x1[(size_t)e * C4 + c4] = s0;
}

// ---------------------------------------------------------------------------
// 5. reduce e2v (+x0, tf32-encode, champion form) with node-range offset.
//    Zeroes d_cnt_n for its own range.
// ---------------------------------------------------------------------------
__global__ __launch_bounds__(64)
void reduce_e2v(const float4* __restrict__ x0, const float4* __restrict__ x1,
                int n_base) {
    const int n   = n_base + blockIdx.x;
    const int tid = threadIdx.x;
    int beg = d_off_n[n];
    int end = d_off_n[n + 1];
    if (tid == 0) d_cnt_n[n] = 0;

    float4 s0 = __ldg(&x0[(size_t)n * C4 + tid]);
    float4 s1 = make_float4(0.f, 0.f, 0.f, 0.f);
    int j = beg;
    for (; j + 1 < end; j += 2) {
        int e0 = __ldg(&d_memb_n[j]);
        int e1 = __ldg(&d_memb_n[j + 1]);
        float4 v0 = __ldg(&x1[(size_t)e0 * C4 + tid]);
        float4 v1 = __ldg(&x1[(size_t)e1 * C4 + tid]);
        s0.x += v0.x; s0.y += v0.y; s0.z += v0.z; s0.w += v0.w;
        s1.x += v1.x; s1.y += v1.y; s1.z += v1.z; s1.w += v1.w;
    }
    if (j < end) {
        int e0 = __ldg(&d_memb_n[j]);
        float4 v0 = __ldg(&x1[(size_t)e0 * C4 + tid]);
        s0.x += v0.x; s0.y += v0.y; s0.z += v0.z; s0.w += v0.w;
    }
    s0.x += s1.x; s0.y += s1.y; s0.z += s1.z; s0.w += s1.w;
    uint4 t;
    t.x = f2tf32(s0.x); t.y = f2tf32(s0.y); t.z = f2tf32(s0.z); t.w = f2tf32(s0.w);
    reinterpret_cast<uint4*>(g_m)[(size_t)n * C4 + tid] = t;
}

// ---------------------------------------------------------------------------
// 6. GEMM (champion form + m_base offset): TF32 mma, BM=128 BN=256 GBK=16,
//    3-stage cp.async, one __syncthreads per k-tile, SPAD=20, unroll-1 loop.
// ---------------------------------------------------------------------------
#define GBM 128
#define GBK 16
#define SPAD 20
#define NTILES (C / GBK)
#define STAGES 3
#define A_WORDS (GBM * SPAD)
#define B_WORDS (256 * SPAD)

__device__ __forceinline__ void cp16(void* smem_dst, const void* gmem_src) {
    uint32_t s = (uint32_t)__cvta_generic_to_shared(smem_dst);
    asm volatile("cp.async.cg.shared.global [%0], [%1], 16;\n" :: "r"(s), "l"(gmem_src));
}
#define CP_COMMIT()   asm volatile("cp.async.commit_group;\n" ::: "memory")
#define CP_WAIT(n)    asm volatile("cp.async.wait_group %0;\n" :: "n"(n) : "memory")

__device__ __forceinline__ void mma_tf32_v(float c[4], const uint32_t a[4], const uint32_t b[2]) {
    asm volatile(
        "mma.sync.aligned.m16n8k8.row.col.f32.tf32.tf32.f32 "
        "{%0,%1,%2,%3}, {%4,%5,%6,%7}, {%8,%9}, {%0,%1,%2,%3};\n"
        : "+f"(c[0]), "+f"(c[1]), "+f"(c[2]), "+f"(c[3])
        : "r"(a[0]), "r"(a[1]), "r"(a[2]), "r"(a[3]), "r"(b[0]), "r"(b[1]));
}

__global__ __launch_bounds__(256, 1)
void gin_gemm_tf32(const float* __restrict__ bias,
                   float* __restrict__ out,
                   int m_base) {
    extern __shared__ uint32_t smem[];   // [STAGES][A_WORDS + B_WORDS]

    const int tid  = threadIdx.x;
    const int lane = tid & 31;
    const int wid  = tid >> 5;
    const int m_off = (wid >> 2) * 64;
    const int n_off = (wid & 3) * 64;
    const int m0 = m_base + blockIdx.x * GBM;

    const int a_row0 = tid >> 2;
    const int a_cq0  = (tid & 3) * 4;
    const int a_row1 = a_row0 + 64;
    const uint32_t* gm = reinterpret_cast<const uint32_t*>(g_m);
    const int b_row0 = tid >> 2;
    const int b_cq0  = (tid & 3) * 4;

    float acc[4][8][4];
    #pragma unroll
    for (int mf = 0; mf < 4; mf++)
        #pragma unroll
        for (int nf = 0; nf < 8; nf++)
            #pragma unroll
            for (int q = 0; q < 4; q++)
                acc[mf][nf][q] = 0.f;

    const int r  = lane >> 2;
    const int cq = lane & 3;

    auto issue_tile = [&](int t, int buf) {
        const int k0 = t * GBK;
        uint32_t* A = smem + buf * (A_WORDS + B_WORDS);
        uint32_t* B = A + A_WORDS;
        cp16(&A[a_row0 * SPAD + a_cq0], &gm[(size_t)(m0 + a_row0) * C + k0 + a_cq0]);
        cp16(&A[a_row1 * SPAD + a_cq0], &gm[(size_t)(m0 + a_row1) * C + k0 + a_cq0]);
        #pragma unroll
        for (int s = 0; s < 4; s++) {
            int row = b_row0 + s * 64;
            cp16(&B[row * SPAD + b_cq0], &g_w[(size_t)row * C + k0 + b_cq0]);
        }
        CP_COMMIT();
    };

    issue_tile(0, 0);
    issue_tile(1, 1);

    #pragma unroll 1
    for (int t = 0; t < NTILES; t++) {
        if (t + 1 < NTILES) { CP_WAIT(1); } else { CP_WAIT(0); }
        __syncthreads();
        if (t + 2 < NTILES) issue_tile(t + 2, (t + 2) % STAGES);

        uint32_t* A = smem + (t % STAGES) * (A_WORDS + B_WORDS);
        uint32_t* B = A + A_WORDS;

        #pragma unroll
        for (int ks = 0; ks < 2; ks++) {
            const int kk = ks * 8;
            uint32_t aF[4][4];
            #pragma unroll
            for (int mf = 0; mf < 4; mf++) {
                int row = m_off + mf * 16 + r;
                aF[mf][0] = A[row * SPAD + kk + cq];
                aF[mf][1] = A[(row + 8) * SPAD + kk + cq];
                aF[mf][2] = A[row * SPAD + kk + cq + 4];
                aF[mf][3] = A[(row + 8) * SPAD + kk + cq + 4];
            }
            #pragma unroll
            for (int nf = 0; nf < 8; nf++) {
                uint32_t bF[2];
                int col = n_off + nf * 8 + r;
                bF[0] = B[col * SPAD + kk + cq];
                bF[1] = B[col * SPAD + kk + cq + 4];
                #pragma unroll
                for (int mf = 0; mf < 4; mf++)
                    mma_tf32_v(acc[mf][nf], aF[mf], bF);
            }
        }
    }

    #pragma unroll
    for (int mf = 0; mf < 4; mf++) {
        #pragma unroll
        for (int nf = 0; nf < 8; nf++) {
            int gc = n_off + nf * 8 + cq * 2;
            float bb0 = bias[gc];
            float bb1 = bias[gc + 1];
            int gr = m0 + m_off + mf * 16 + r;
            if (gr < N_NODES) {
                float2 v = make_float2(acc[mf][nf][0] + bb0, acc[mf][nf][1] + bb1);
                *reinterpret_cast<float2*>(&out[(size_t)gr * C + gc]) = v;
            }
            if (gr + 8 < N_NODES) {
                float2 v = make_float2(acc[mf][nf][2] + bb0, acc[mf][nf][3] + bb1);
                *reinterpret_cast<float2*>(&out[(size_t)(gr + 8) * C + gc]) = v;
            }
        }
    }
}

#define GEMM_SMEM_BYTES (STAGES * (A_WORDS + B_WORDS) * 4)

// ---------------------------------------------------------------------------
// Launch: node-side CSR chain forked on s2; e2v/GEMM split into halves so
// gemm(H0) on s2 overlaps e2v(H1) on main.
// ---------------------------------------------------------------------------
extern "C" void kernel_launch(void* const* d_in, const int* in_sizes, int n_in,
                              void* d_out, int out_size) {
    const float* x0       = (const float*)d_in[0];
    const int*   node_idx = (const int*)d_in[1];
    const int*   edge_idx = (const int*)d_in[2];
    const float* W        = (const float*)d_in[3];
    const float* b        = (const float*)d_in[4];

    float* out = (float*)d_out;
    float* x1  = out + (size_t)N_NODES * C;

    static cudaStream_t s2 = nullptr;
    static cudaEvent_t  evFork = nullptr, evJoin = nullptr, evA = nullptr, evB = nullptr;
    if (s2 == nullptr) {
        cudaStreamCreateWithFlags(&s2, cudaStreamNonBlocking);
        cudaEventCreateWithFlags(&evFork, cudaEventDisableTiming);
        cudaEventCreateWithFlags(&evJoin, cudaEventDisableTiming);
        cudaEventCreateWithFlags(&evA, cudaEventDisableTiming);
        cudaEventCreateWithFlags(&evB, cudaEventDisableTiming);
        cudaFuncSetAttribute(gin_gemm_tf32,
                             cudaFuncAttributeMaxDynamicSharedMemorySize,
                             GEMM_SMEM_BYTES);
    }

    // ---- fork: node-side CSR chain on s2 ----
    cudaEventRecord(evFork, 0);
    cudaStreamWaitEvent(s2, evFork, 0);
    hist_n_kernel<<<800, 256, 0, s2>>>(node_idx,
                                       reinterpret_cast<const float4*>(W));
    scan_one_kernel<<<1, 1024, 0, s2>>>(1);
    fill_n_kernel<<<800, 256, 0, s2>>>(node_idx, edge_idx);
    cudaEventRecord(evJoin, s2);

    // ---- edge-side chain + v2e on default stream ----
    hist_e_kernel<<<800, 256>>>(edge_idx);
    scan_one_kernel<<<1, 1024>>>(0);
    fill_e_kernel<<<800, 256>>>(node_idx, edge_idx);
    {
        dim3 grid(N_EDGES / 2, 2);
        reduce_v2e_half<<<grid, 64>>>(reinterpret_cast<const float4*>(x0),
                                      reinterpret_cast<float4*>(x1));
    }

    // ---- join node chain, then pipelined e2v/GEMM halves ----
    cudaStreamWaitEvent(0, evJoin, 0);

    // e2v half 0 on main
    reduce_e2v<<<N_HALF, 64>>>(reinterpret_cast<const float4*>(x0),
                               reinterpret_cast<const float4*>(x1), 0);
    cudaEventRecord(evA, 0);

    // gemm half 0 on s2 (waits e2v H0), overlapping e2v half 1 on main
    cudaStreamWaitEvent(s2, evA, 0);
    gin_gemm_tf32<<<N_HALF / GBM, 256, GEMM_SMEM_BYTES, s2>>>(b, out, 0);
    cudaEventRecord(evB, s2);

    reduce_e2v<<<N_NODES - N_HALF, 64>>>(reinterpret_cast<const float4*>(x0),
                                         reinterpret_cast<const float4*>(x1),
                                         N_HALF);

    // gemm half 1 on main
    gin_gemm_tf32<<<(N_NODES_PAD - N_HALF) / GBM, 256, GEMM_SMEM_BYTES>>>(b, out, N_HALF);

    // main must also wait for gemm half 0
    cudaStreamWaitEvent(0, evB, 0);
}

// round 17
// speedup vs baseline: 1.4126x; 1.0053x over previous
#include <cuda_runtime.h>
#include <cstdint>

#define N_NODES 100000
#define N_NODES_PAD 100096   // 782 * 128, padded so GEMM A tiles never go OOB
#define N_EDGES 50000
#define NNZ     800000
#define C       256
#define C4      (C / 4)   // 64 float4 per row

// ---------------- scratch (__device__ globals: allowed) ----------------
__device__ float    g_m[(size_t)N_NODES_PAD * C];  // tf32-encoded (x0 + m)
__device__ uint32_t g_w[(size_t)C * C];            // tf32-encoded W
__device__ int   d_cnt_e[N_EDGES];
__device__ int   d_cnt_n[N_NODES];
__device__ int   d_off_e[N_EDGES + 1];
__device__ int   d_off_n[N_NODES + 1];
__device__ int   d_memb_e[NNZ];                // node ids grouped by edge
__device__ int   d_memb_n[NNZ];                // edge ids grouped by node

__device__ __forceinline__ uint32_t f2tf32(float f) {
    uint32_t r;
    asm("cvt.rna.tf32.f32 %0, %1;" : "=r"(r) : "f"(f));
    return r;
}

// ---------------------------------------------------------------------------
// 1a. edge-side histogram
// ---------------------------------------------------------------------------
__global__ void hist_e_kernel(const int* __restrict__ edge_idx) {
    int idx = blockIdx.x * blockDim.x + threadIdx.x;
    int stride = gridDim.x * blockDim.x;
    for (int i = idx; i < NNZ; i += stride)
        atomicAdd(&d_cnt_e[edge_idx[i]], 1);
}

// ---------------------------------------------------------------------------
// 1b. node-side histogram + W->tf32 conversion folded in
// ---------------------------------------------------------------------------
__global__ void hist_n_kernel(const int* __restrict__ node_idx,
                              const float4* __restrict__ W) {
    int idx = blockIdx.x * blockDim.x + threadIdx.x;

    if (idx < C * C / 4) {
        float4 v = W[idx];
        uint4 t;
        t.x = f2tf32(v.x); t.y = f2tf32(v.y); t.z = f2tf32(v.z); t.w = f2tf32(v.w);
        reinterpret_cast<uint4*>(g_w)[idx] = t;
    }

    int stride = gridDim.x * blockDim.x;
    for (int i = idx; i < NNZ; i += stride)
        atomicAdd(&d_cnt_n[node_idx[i]], 1);
}

// ---------------------------------------------------------------------------
// 2. exclusive scan, VT=4 (int4) — one side per launch (0=edge, 1=node)
// ---------------------------------------------------------------------------
__global__ __launch_bounds__(1024)
void scan_one_kernel(int which) {
    int* cnt;
    int* off;
    int  L;
    if (which == 0) { cnt = d_cnt_e; off = d_off_e; L = N_EDGES; }
    else            { cnt = d_cnt_n; off = d_off_n; L = N_NODES; }

    const int tid  = threadIdx.x;
    const int lane = tid & 31;
    const int wid  = tid >> 5;
    __shared__ int warp_sum[32];

    const int L4 = L >> 2;
    int running = 0;
    for (int base4 = 0; base4 < L4; base4 += 1024) {
        int i4 = base4 + tid;
        int4 v = make_int4(0, 0, 0, 0);
        if (i4 < L4) v = reinterpret_cast<const int4*>(cnt)[i4];
        int p0 = v.x;
        int p1 = p0 + v.y;
        int p2 = p1 + v.z;
        int p3 = p2 + v.w;
        int tot = p3;
        int w = tot;
        #pragma unroll
        for (int d = 1; d < 32; d <<= 1) {
            int t = __shfl_up_sync(0xffffffffu, w, d);
            if (lane >= d) w += t;
        }
        if (lane == 31) warp_sum[wid] = w;
        __syncthreads();
        if (wid == 0) {
            int ws = warp_sum[lane];
            #pragma unroll
            for (int d = 1; d < 32; d <<= 1) {
                int t = __shfl_up_sync(0xffffffffu, ws, d);
                if (lane >= d) ws += t;
            }
            warp_sum[lane] = ws;
        }
        __syncthreads();
        int excl = (w - tot) + (wid > 0 ? warp_sum[wid - 1] : 0) + running;
        if (i4 < L4) {
            int i = i4 * 4;
            off[i + 1] = excl + p0;
            off[i + 2] = excl + p1;
            off[i + 3] = excl + p2;
            off[i + 4] = excl + p3;
        }
        running += warp_sum[31];
        __syncthreads();
    }
    if (tid == 0) off[0] = 0;
    for (int i = tid; i < L; i += 1024) cnt[i] = 0;
}

// ---------------------------------------------------------------------------
// 3a/3b. fill member lists
// ---------------------------------------------------------------------------
__global__ void fill_e_kernel(const int* __restrict__ node_idx,
                              const int* __restrict__ edge_idx) {
    int idx = blockIdx.x * blockDim.x + threadIdx.x;
    int stride = gridDim.x * blockDim.x;
    for (int i = idx; i < NNZ; i += stride) {
        int n = node_idx[i];
        int e = edge_idx[i];
        int re = atomicAdd(&d_cnt_e[e], 1);
        d_memb_e[d_off_e[e] + re] = n;
    }
}

__global__ void fill_n_kernel(const int* __restrict__ node_idx,
                              const int* __restrict__ edge_idx) {
    int idx = blockIdx.x * blockDim.x + threadIdx.x;
    int stride = gridDim.x * blockDim.x;
    for (int i = idx; i < NNZ; i += stride) {
        int n = node_idx[i];
        int e = edge_idx[i];
        int rn = atomicAdd(&d_cnt_n[n], 1);
        d_memb_n[d_off_n[n] + rn] = e;
    }
}

// ---------------------------------------------------------------------------
// 4. reduce v2e, channel-split (champion form). Zeroes d_cnt_e in pass 0.
// ---------------------------------------------------------------------------
__global__ __launch_bounds__(64)
void reduce_v2e_half(const float4* __restrict__ x0, float4* __restrict__ x1) {
    const int tid  = threadIdx.x;
    const int e    = blockIdx.x * 2 + (tid >> 5);
    const int lane = tid & 31;
    const int c4   = blockIdx.y * 32 + lane;
    if (blockIdx.y == 0 && lane == 0) d_cnt_e[e] = 0;

    int beg = __ldg(&d_off_e[e]);
    int end = __ldg(&d_off_e[e + 1]);

    float4 s0 = make_float4(0.f, 0.f, 0.f, 0.f);
    float4 s1 = make_float4(0.f, 0.f, 0.f, 0.f);
    int j = beg;
    for (; j + 1 < end; j += 2) {
        int n0 = __ldg(&d_memb_e[j]);
        int n1 = __ldg(&d_memb_e[j + 1]);
        float4 v0 = __ldg(&x0[(size_t)n0 * C4 + c4]);
        float4 v1 = __ldg(&x0[(size_t)n1 * C4 + c4]);
        s0.x += v0.x; s0.y += v0.y; s0.z += v0.z; s0.w += v0.w;
        s1.x += v1.x; s1.y += v1.y; s1.z += v1.z; s1.w += v1.w;
    }
    if (j < end) {
        int n0 = __ldg(&d_memb_e[j]);
        float4 v0 = __ldg(&x0[(size_t)n0 * C4 + c4]);
        s0.x += v0.x; s0.y += v0.y; s0.z += v0.z; s0.w += v0.w;
    }
    s0.x += s1.x; s0.y += s1.y; s0.z += s1.z; s0.w += s1.w;
    x1[(size_t)e * C4 + c4] = s0;
}

// ---------------------------------------------------------------------------
// 5. reduce e2v (+x0, tf32-encode, champion form). Zeroes d_cnt_n.
// ---------------------------------------------------------------------------
__global__ __launch_bounds__(64)
void reduce_e2v(const float4* __restrict__ x0, const float4* __restrict__ x1) {
    const int n   = blockIdx.x;
    const int tid = threadIdx.x;
    int beg = d_off_n[n];
    int end = d_off_n[n + 1];
    if (tid == 0) d_cnt_n[n] = 0;

    float4 s0 = __ldg(&x0[(size_t)n * C4 + tid]);
    float4 s1 = make_float4(0.f, 0.f, 0.f, 0.f);
    int j = beg;
    for (; j + 1 < end; j += 2) {
        int e0 = __ldg(&d_memb_n[j]);
        int e1 = __ldg(&d_memb_n[j + 1]);
        float4 v0 = __ldg(&x1[(size_t)e0 * C4 + tid]);
        float4 v1 = __ldg(&x1[(size_t)e1 * C4 + tid]);
        s0.x += v0.x; s0.y += v0.y; s0.z += v0.z; s0.w += v0.w;
        s1.x += v1.x; s1.y += v1.y; s1.z += v1.z; s1.w += v1.w;
    }
    if (j < end) {
        int e0 = __ldg(&d_memb_n[j]);
        float4 v0 = __ldg(&x1[(size_t)e0 * C4 + tid]);
        s0.x += v0.x; s0.y += v0.y; s0.z += v0.z; s0.w += v0.w;
    }
    s0.x += s1.x; s0.y += s1.y; s0.z += s1.z; s0.w += s1.w;
    uint4 t;
    t.x = f2tf32(s0.x); t.y = f2tf32(s0.y); t.z = f2tf32(s0.z); t.w = f2tf32(s0.w);
    reinterpret_cast<uint4*>(g_m)[(size_t)n * C4 + tid] = t;
}

// ---------------------------------------------------------------------------
// 6. GEMM (champion form, STAGES 3 -> 5): TF32 mma, BM=128 BN=256 GBK=16,
//    5-stage cp.async pipeline, one __syncthreads per k-tile, SPAD=20,
//    `#pragma unroll 1` outer loop (load-bearing).
// ---------------------------------------------------------------------------
#define GBM 128
#define GBK 16
#define SPAD 20
#define NTILES (C / GBK)
#define STAGES 5
#define A_WORDS (GBM * SPAD)
#define B_WORDS (256 * SPAD)

__device__ __forceinline__ void cp16(void* smem_dst, const void* gmem_src) {
    uint32_t s = (uint32_t)__cvta_generic_to_shared(smem_dst);
    asm volatile("cp.async.cg.shared.global [%0], [%1], 16;\n" :: "r"(s), "l"(gmem_src));
}
#define CP_COMMIT()   asm volatile("cp.async.commit_group;\n" ::: "memory")
#define CP_WAIT(n)    asm volatile("cp.async.wait_group %0;\n" :: "n"(n) : "memory")

__device__ __forceinline__ void mma_tf32_v(float c[4], const uint32_t a[4], const uint32_t b[2]) {
    asm volatile(
        "mma.sync.aligned.m16n8k8.row.col.f32.tf32.tf32.f32 "
        "{%0,%1,%2,%3}, {%4,%5,%6,%7}, {%8,%9}, {%0,%1,%2,%3};\n"
        : "+f"(c[0]), "+f"(c[1]), "+f"(c[2]), "+f"(c[3])
        : "r"(a[0]), "r"(a[1]), "r"(a[2]), "r"(a[3]), "r"(b[0]), "r"(b[1]));
}

__global__ __launch_bounds__(256, 1)
void gin_gemm_tf32(const float* __restrict__ bias,
                   float* __restrict__ out) {
    extern __shared__ uint32_t smem[];   // [STAGES][A_WORDS + B_WORDS]

    const int tid  = threadIdx.x;
    const int lane = tid & 31;
    const int wid  = tid >> 5;
    const int m_off = (wid >> 2) * 64;
    const int n_off = (wid & 3) * 64;
    const int m0 = blockIdx.x * GBM;

    const int a_row0 = tid >> 2;
    const int a_cq0  = (tid & 3) * 4;
    const int a_row1 = a_row0 + 64;
    const uint32_t* gm = reinterpret_cast<const uint32_t*>(g_m);
    const int b_row0 = tid >> 2;
    const int b_cq0  = (tid & 3) * 4;

    float acc[4][8][4];
    #pragma unroll
    for (int mf = 0; mf < 4; mf++)
        #pragma unroll
        for (int nf = 0; nf < 8; nf++)
            #pragma unroll
            for (int q = 0; q < 4; q++)
                acc[mf][nf][q] = 0.f;

    const int r  = lane >> 2;
    const int cq = lane & 3;

    auto issue_tile = [&](int t, int buf) {
        const int k0 = t * GBK;
        uint32_t* A = smem + buf * (A_WORDS + B_WORDS);
        uint32_t* B = A + A_WORDS;
        cp16(&A[a_row0 * SPAD + a_cq0], &gm[(size_t)(m0 + a_row0) * C + k0 + a_cq0]);
        cp16(&A[a_row1 * SPAD + a_cq0], &gm[(size_t)(m0 + a_row1) * C + k0 + a_cq0]);
        #pragma unroll
        for (int s = 0; s < 4; s++) {
            int row = b_row0 + s * 64;
            cp16(&B[row * SPAD + b_cq0], &g_w[(size_t)row * C + k0 + b_cq0]);
        }
        CP_COMMIT();
    };

    issue_tile(0, 0);
    issue_tile(1, 1);
    issue_tile(2, 2);
    issue_tile(3, 3);

    #pragma unroll 1
    for (int t = 0; t < NTILES; t++) {
        // tile t must be complete; leave up to min(3, NTILES-1-t) groups pending
        int rem = NTILES - 1 - t;
        if (rem >= 3)      { CP_WAIT(3); }
        else if (rem == 2) { CP_WAIT(2); }
        else if (rem == 1) { CP_WAIT(1); }
        else               { CP_WAIT(0); }
        __syncthreads();
        if (t + 4 < NTILES) issue_tile(t + 4, (t + 4) % STAGES);

        uint32_t* A = smem + (t % STAGES) * (A_WORDS + B_WORDS);
        uint32_t* B = A + A_WORDS;

        #pragma unroll
        for (int ks = 0; ks < 2; ks++) {
            const int kk = ks * 8;
            uint32_t aF[4][4];
            #pragma unroll
            for (int mf = 0; mf < 4; mf++) {
                int row = m_off + mf * 16 + r;
                aF[mf][0] = A[row * SPAD + kk + cq];
                aF[mf][1] = A[(row + 8) * SPAD + kk + cq];
                aF[mf][2] = A[row * SPAD + kk + cq + 4];
                aF[mf][3] = A[(row + 8) * SPAD + kk + cq + 4];
            }
            #pragma unroll
            for (int nf = 0; nf < 8; nf++) {
                uint32_t bF[2];
                int col = n_off + nf * 8 + r;
                bF[0] = B[col * SPAD + kk + cq];
                bF[1] = B[col * SPAD + kk + cq + 4];
                #pragma unroll
                for (int mf = 0; mf < 4; mf++)
                    mma_tf32_v(acc[mf][nf], aF[mf], bF);
            }
        }
    }

    #pragma unroll
    for (int mf = 0; mf < 4; mf++) {
        #pragma unroll
        for (int nf = 0; nf < 8; nf++) {
            int gc = n_off + nf * 8 + cq * 2;
            float bb0 = bias[gc];
            float bb1 = bias[gc + 1];
            int gr = m0 + m_off + mf * 16 + r;
            if (gr < N_NODES) {
                float2 v = make_float2(acc[mf][nf][0] + bb0, acc[mf][nf][1] + bb1);
                *reinterpret_cast<float2*>(&out[(size_t)gr * C + gc]) = v;
            }
            if (gr + 8 < N_NODES) {
                float2 v = make_float2(acc[mf][nf][2] + bb0, acc[mf][nf][3] + bb1);
                *reinterpret_cast<float2*>(&out[(size_t)(gr + 8) * C + gc]) = v;
            }
        }
    }
}

#define GEMM_SMEM_BYTES (STAGES * (A_WORDS + B_WORDS) * 4)

// ---------------------------------------------------------------------------
// Launch: node-side CSR chain forked on s2 (champion topology),
// single e2v + single GEMM tail.
// ---------------------------------------------------------------------------
extern "C" void kernel_launch(void* const* d_in, const int* in_sizes, int n_in,
                              void* d_out, int out_size) {
    const float* x0       = (const float*)d_in[0];
    const int*   node_idx = (const int*)d_in[1];
    const int*   edge_idx = (const int*)d_in[2];
    const float* W        = (const float*)d_in[3];
    const float* b        = (const float*)d_in[4];

    float* out = (float*)d_out;
    float* x1  = out + (size_t)N_NODES * C;

    static cudaStream_t s2 = nullptr;
    static cudaEvent_t  evFork = nullptr, evJoin = nullptr;
    if (s2 == nullptr) {
        cudaStreamCreateWithFlags(&s2, cudaStreamNonBlocking);
        cudaEventCreateWithFlags(&evFork, cudaEventDisableTiming);
        cudaEventCreateWithFlags(&evJoin, cudaEventDisableTiming);
        cudaFuncSetAttribute(gin_gemm_tf32,
                             cudaFuncAttributeMaxDynamicSharedMemorySize,
                             GEMM_SMEM_BYTES);
    }

    // ---- fork: node-side CSR chain on s2 ----
    cudaEventRecord(evFork, 0);
    cudaStreamWaitEvent(s2, evFork, 0);
    hist_n_kernel<<<800, 256, 0, s2>>>(node_idx,
                                       reinterpret_cast<const float4*>(W));
    scan_one_kernel<<<1, 1024, 0, s2>>>(1);
    fill_n_kernel<<<800, 256, 0, s2>>>(node_idx, edge_idx);
    cudaEventRecord(evJoin, s2);

    // ---- edge-side chain + v2e on default stream ----
    hist_e_kernel<<<800, 256>>>(edge_idx);
    scan_one_kernel<<<1, 1024>>>(0);
    fill_e_kernel<<<800, 256>>>(node_idx, edge_idx);
    {
        dim3 grid(N_EDGES / 2, 2);
        reduce_v2e_half<<<grid, 64>>>(reinterpret_cast<const float4*>(x0),
                                      reinterpret_cast<float4*>(x1));
    }

    // ---- join, then e2v + GEMM ----
    cudaStreamWaitEvent(0, evJoin, 0);
    reduce_e2v<<<N_NODES, 64>>>(reinterpret_cast<const float4*>(x0),
                                reinterpret_cast<const float4*>(x1));

    gin_gemm_tf32<<<N_NODES_PAD / GBM, 256, GEMM_SMEM_BYTES>>>(b, out);
}